// round 13
// baseline (speedup 1.0000x reference)
#include <cuda_runtime.h>
#include <math.h>

#define BDIM   128
#define TENC   64
#define TDEC   32
#define DIN    2048
#define DW     300
#define HID    512
#define G4     2048   // 4*HID
#define NBLK   128    // persistent grid: 4 b-groups x 32 j-groups

typedef unsigned long long u64;

// ---------------- scratch (device globals: no allocation allowed) -------------
// Referenced ONLY from device code (host-side symbol use = ATS shadow bug).
__device__ float g_pre_enc[BDIM * TENC * G4];   // [b*TENC + t][4H]
__device__ float g_pre_dec[BDIM * TDEC * G4];   // [b*TDEC + t][4H]
__device__ float g_hT[2][HID][BDIM];            // TRANSPOSED hidden state [k][b]
__device__ float g_c[BDIM * HID];               // cell state [b][j]
__device__ float g_dechs[TDEC * BDIM * HID];    // decoder h outputs [t][b][h]

// grid barrier state (count returns to 0 after each barrier)
__device__ unsigned g_bar_count = 0;
__device__ volatile unsigned g_bar_gen = 0;

__device__ __forceinline__ float sigm(float x) { return 1.0f / (1.0f + expf(-x)); }

__device__ __forceinline__ u64 ffma2(u64 a, u64 b, u64 c) {
    u64 d;
    asm("fma.rn.f32x2 %0, %1, %2, %3;" : "=l"(d) : "l"(a), "l"(b), "l"(c));
    return d;
}
__device__ __forceinline__ u64 fadd2(u64 a, u64 b) {
    u64 d;
    asm("add.rn.f32x2 %0, %1, %2;" : "=l"(d) : "l"(a), "l"(b));
    return d;
}
__device__ __forceinline__ u64 dup2(float w) {
    u64 d;
    asm("mov.b64 %0, {%1, %1};" : "=l"(d) : "f"(w));
    return d;
}

// two-phase sense-reversing grid barrier; all NBLK blocks co-resident
// (1 block/SM, 128 blocks <= 148 SMs). __nanosleep backoff in the spin is
// load-bearing: a tight volatile poll from 128 blocks hammers one L2 line.
__device__ __forceinline__ void grid_sync() {
    __syncthreads();
    if (threadIdx.x == 0) {
        __threadfence();
        unsigned my = g_bar_gen;
        if (atomicAdd(&g_bar_count, 1) == NBLK - 1) {
            g_bar_count = 0;
            __threadfence();
            g_bar_gen = my + 1;
        } else {
            while (g_bar_gen == my) { __nanosleep(64); }
        }
        __threadfence();
    }
    __syncthreads();
}

// ---------------- double-buffered packed-f32x2 GEMM:  C = A @ W + bias --------
// 128x128 tile, BK=8, 256 threads, one __syncthreads per k-tile.
template <int MODE>
__global__ __launch_bounds__(256, 2)
void gemm_kernel(const float* __restrict__ A, const float* __restrict__ W,
                 const float* __restrict__ bias, float* __restrict__ Cout,
                 const int* __restrict__ ids, int M, int N, int K)
{
    __shared__ float As[2][8][132];
    __shared__ float Bs[2][8][128];

    float* C;
    if (MODE == 0)      C = g_pre_enc;
    else if (MODE == 1) C = g_pre_dec;
    else                C = Cout;

    const int bn0 = blockIdx.x * 128;
    const int bm0 = blockIdx.y * 128;
    const int tid = threadIdx.x;

    const int arow = tid >> 1;          // 0..127
    const int ak   = (tid & 1) * 4;     // 0 or 4
    const int bk   = tid >> 5;          // 0..7
    const int bn   = (tid & 31) * 4;    // 0..124

    const float* arow_ptr;
    if (MODE == 1) {
        arow_ptr = A + (long)ids[bm0 + arow] * K;     // embedding gather
    } else if (MODE == 2) {
        arow_ptr = g_dechs + (long)(bm0 + arow) * K;
    } else {
        arow_ptr = A + (long)(bm0 + arow) * K;
    }

    const int tc = tid & 15;
    const int tr = tid >> 4;

    u64 acc[8][4];
    #pragma unroll
    for (int i = 0; i < 8; i++)
        #pragma unroll
        for (int j = 0; j < 4; j++) acc[i][j] = 0ull;

    // prologue: stage tile 0
    #pragma unroll
    for (int s = 0; s < 4; s++) {
        int k = ak + s;
        As[0][ak + s][arow] = (k < K) ? arow_ptr[k] : 0.0f;
    }
    #pragma unroll
    for (int s = 0; s < 4; s++) {
        int col = bn0 + bn + s;
        Bs[0][bk][bn + s] = (bk < K && col < N) ? W[(long)bk * N + col] : 0.0f;
    }
    __syncthreads();

    for (int kt = 0; kt < K; kt += 8) {
        const int cur = (kt >> 3) & 1;
        const bool has_next = (kt + 8) < K;

        // prefetch next tile into registers (latency overlaps compute)
        float ra[4], rb[4];
        if (has_next) {
            #pragma unroll
            for (int s = 0; s < 4; s++) {
                int k = kt + 8 + ak + s;
                ra[s] = (k < K) ? arow_ptr[k] : 0.0f;
            }
            #pragma unroll
            for (int s = 0; s < 4; s++) {
                int k = kt + 8 + bk;
                int col = bn0 + bn + s;
                rb[s] = (k < K && col < N) ? W[(long)k * N + col] : 0.0f;
            }
        }

        #pragma unroll
        for (int k = 0; k < 8; k++) {
            float4 a0 = *reinterpret_cast<const float4*>(&As[cur][k][tr * 8]);
            float4 a1 = *reinterpret_cast<const float4*>(&As[cur][k][tr * 8 + 4]);
            u64 a2[8];
            a2[0] = dup2(a0.x); a2[1] = dup2(a0.y);
            a2[2] = dup2(a0.z); a2[3] = dup2(a0.w);
            a2[4] = dup2(a1.x); a2[5] = dup2(a1.y);
            a2[6] = dup2(a1.z); a2[7] = dup2(a1.w);
            const u64* bp = reinterpret_cast<const u64*>(&Bs[cur][k][0]);
            u64 b2[4];
            #pragma unroll
            for (int j = 0; j < 4; j++) b2[j] = bp[tc + 16 * j];
            #pragma unroll
            for (int i = 0; i < 8; i++)
                #pragma unroll
                for (int j = 0; j < 4; j++)
                    acc[i][j] = ffma2(a2[i], b2[j], acc[i][j]);
        }

        if (has_next) {
            #pragma unroll
            for (int s = 0; s < 4; s++) As[1 - cur][ak + s][arow] = ra[s];
            #pragma unroll
            for (int s = 0; s < 4; s++) Bs[1 - cur][bk][bn + s] = rb[s];
        }
        __syncthreads();
    }

    #pragma unroll
    for (int i = 0; i < 8; i++) {
        int m = bm0 + tr * 8 + i;
        #pragma unroll
        for (int j = 0; j < 4; j++) {
            float2 v = *reinterpret_cast<float2*>(&acc[i][j]);
            int n = bn0 + 2 * (tc + 16 * j);
            if (MODE == 2) {
                int b = m & 127, t = m >> 7;    // m = t*128 + b
                long obase = ((long)b * TDEC + t) * (long)N;
                if (n < N)     C[obase + n]     = v.x + bias[n];
                if (n + 1 < N) C[obase + n + 1] = v.y + bias[n + 1];
            } else {
                float* cp = C + (long)m * N + n;
                cp[0] = v.x + bias[n];
                cp[1] = v.y + bias[n + 1];
            }
        }
    }
}

// ---------------- persistent recurrent LSTM (j-pair packed) -------------------
// Block (bg, jg): b0 = bg*32 (32 batches), j0 = jg*16 (16 j as 8 j-pairs x 4 gates).
// 512 threads = 2 k-halves x (8 jp x 32 b). Warp = fixed jp, lanes = batches:
//   weight fetch per k = 2x LDS.128 BROADCAST (32B), h = LDS.32 lane-consec + dup.
// Weights resident in smem all phase. h in transposed global g_hT[k][b].
//
// Dynamic smem:
//   Ws  float[512][64]   131072 B  : Ws[k][jp*8 + g*2 + e] = W[k][g*512+j0+2jp+e]
//   hs  float[512][36]    73728 B  : padded transposed h staging
//   red u64[256][4] aliased on hs (8 KB, used only after compute)
#define SM_WS_BYTES  (512 * 64 * 4)
#define SM_TOTAL     (SM_WS_BYTES + 512 * 36 * 4)

__global__ __launch_bounds__(512, 1)
void lstm_persistent_kernel(const float* __restrict__ WhE,
                            const float* __restrict__ WhD)
{
    extern __shared__ char smraw[];
    float (*Ws)[64] = reinterpret_cast<float(*)[64]>(smraw);
    float (*hs)[36] = reinterpret_cast<float(*)[36]>(smraw + SM_WS_BYTES);
    u64   (*red)[4] = reinterpret_cast<u64(*)[4]>(smraw + SM_WS_BYTES);

    const int tid  = threadIdx.x;
    const int half = tid >> 8;          // k in [0,256) / [256,512)
    const int ltid = tid & 255;
    const int b0 = blockIdx.x * 32;
    const int j0 = blockIdx.y * 16;

    const int jp = ltid >> 5;           // 0..7  (j-pair: j0+2jp, j0+2jp+1)
    const int b  = ltid & 31;           // 0..31 (lane = batch)

    // h staging roles: 512 threads, b-lane consecutive
    const int sb = tid & 31;            // batch lane
    const int sk = tid >> 5;            // k row 0..15 (+ it*16)

    // ---- init: zero h[0] (transposed) and c for this block's slice ----
    if (half == 0) {
        int j = j0 + 2 * jp;
        g_hT[0][j][b0 + b] = 0.0f;
        g_hT[0][j + 1][b0 + b] = 0.0f;
        *reinterpret_cast<float2*>(&g_c[(b0 + b) * HID + j]) = make_float2(0.f, 0.f);
    }

    // ---- load encoder weight slice into smem ----
    for (int idx = tid; idx < 512 * 64; idx += 512) {
        int k = idx >> 6, col = idx & 63;
        int jpl = col >> 3, g = (col >> 1) & 3, e = col & 1;
        Ws[k][col] = WhE[(long)k * G4 + g * HID + j0 + 2 * jpl + e];
    }
    // first grid_sync's __syncthreads covers Ws visibility within the block

    for (int s = 0; s < TENC + TDEC; s++) {
        const int phase = (s >= TENC);
        const int t = phase ? s - TENC : s;
        const float* pre = phase ? g_pre_dec : g_pre_enc;
        const int Tdim = phase ? TDEC : TENC;
        const float (*hinT)[BDIM] = g_hT[s & 1];
        float (*houtT)[BDIM] = g_hT[(s + 1) & 1];
        float* dechs = phase ? (g_dechs + (long)t * BDIM * HID) : (float*)0;

        grid_sync();   // previous step's hT visible everywhere

        if (s == TENC) {   // phase switch: decoder weights
            for (int idx = tid; idx < 512 * 64; idx += 512) {
                int k = idx >> 6, col = idx & 63;
                int jpl = col >> 3, g = (col >> 1) & 3, e = col & 1;
                Ws[k][col] = WhD[(long)k * G4 + g * HID + j0 + 2 * jpl + e];
            }
            __syncthreads();
        }

        // ---- stage h: hs[k][b] = hT[k][b0+b] (coalesced LDG, conflict-free STS)
        #pragma unroll 4
        for (int it = 0; it < 32; it++) {
            int k = sk + it * 16;
            hs[k][sb] = hinT[k][b0 + sb];
        }
        __syncthreads();

        // ---- prefetch pre-activation gates + c (latency hidden by k-loop) ----
        float2 pg[4], c2;
        if (half == 0) {
            const float* pr = pre + ((long)(b0 + b) * Tdim + t) * G4 + j0 + 2 * jp;
            pg[0] = *reinterpret_cast<const float2*>(pr);
            pg[1] = *reinterpret_cast<const float2*>(pr + 512);
            pg[2] = *reinterpret_cast<const float2*>(pr + 1024);
            pg[3] = *reinterpret_cast<const float2*>(pr + 1536);
            c2 = *reinterpret_cast<const float2*>(&g_c[(b0 + b) * HID + j0 + 2 * jp]);
        }

        // ---- main FMA loop: per k = LDS.32 + dup + 2x LDS.128(bcast) + 4 ffma2
        u64 acc2[4] = {0ull, 0ull, 0ull, 0ull};
        const int kbase = half << 8;
        #pragma unroll 8
        for (int k = kbase; k < kbase + 256; k++) {
            u64 h2 = dup2(hs[k][b]);
            ulonglong2 w01 = *reinterpret_cast<const ulonglong2*>(&Ws[k][jp * 8]);
            ulonglong2 w23 = *reinterpret_cast<const ulonglong2*>(&Ws[k][jp * 8 + 4]);
            acc2[0] = ffma2(h2, w01.x, acc2[0]);
            acc2[1] = ffma2(h2, w01.y, acc2[1]);
            acc2[2] = ffma2(h2, w23.x, acc2[2]);
            acc2[3] = ffma2(h2, w23.y, acc2[3]);
        }
        __syncthreads();   // compute done before red aliases hs

        if (half == 1) {
            #pragma unroll
            for (int g = 0; g < 4; g++) red[ltid][g] = acc2[g];
        }
        __syncthreads();

        if (half == 0) {
            float2 av[4];
            #pragma unroll
            for (int g = 0; g < 4; g++) {
                u64 v = fadd2(acc2[g], red[ltid][g]);
                av[g] = *reinterpret_cast<float2*>(&v);
            }
            // av[g] = (j = j0+2jp, j0+2jp+1); batch = b0+b
            int bb = b0 + b;
            int j = j0 + 2 * jp;
            float hn[2], cn[2];
            #pragma unroll
            for (int e = 0; e < 2; e++) {
                float gi = (e ? av[0].y : av[0].x) + (e ? pg[0].y : pg[0].x);
                float gj = (e ? av[1].y : av[1].x) + (e ? pg[1].y : pg[1].x);
                float gf = (e ? av[2].y : av[2].x) + (e ? pg[2].y : pg[2].x);
                float go = (e ? av[3].y : av[3].x) + (e ? pg[3].y : pg[3].x);
                float cv = e ? c2.y : c2.x;
                cn[e] = cv * sigm(gf + 1.0f) + sigm(gi) * tanhf(gj);
                hn[e] = tanhf(cn[e]) * sigm(go);
            }
            *reinterpret_cast<float2*>(&g_c[bb * HID + j]) = make_float2(cn[0], cn[1]);
            houtT[j][bb]     = hn[0];
            houtT[j + 1][bb] = hn[1];
            if (dechs)
                *reinterpret_cast<float2*>(&dechs[bb * HID + j]) =
                    make_float2(hn[0], hn[1]);
        }
    }
}

// ---------------- launch ------------------------------------------------------
extern "C" void kernel_launch(void* const* d_in, const int* in_sizes, int n_in,
                              void* d_out, int out_size) {
    (void)out_size;
    const float* frames  = 0;   // 16777216
    const int*   cap_ids = 0;   // 4096
    const float* emb     = 0;   // 9600000
    const float* W_enc   = 0;   // 5242880
    const float* b_enc   = 0;   // 2048 (first seen)
    const float* W_dec   = 0;   // 1662976
    const float* b_dec   = 0;   // 2048 (second seen)
    const float* W_out   = 0;   // 153600
    const float* b_out   = 0;   // 300

    for (int i = 0; i < n_in; i++) {
        long sz = in_sizes[i];
        const void* p = d_in[i];
        if      (sz == 16777216) frames  = (const float*)p;
        else if (sz == 4096)     cap_ids = (const int*)p;
        else if (sz == 9600000)  emb     = (const float*)p;
        else if (sz == 5242880)  W_enc   = (const float*)p;
        else if (sz == 1662976)  W_dec   = (const float*)p;
        else if (sz == 153600)   W_out   = (const float*)p;
        else if (sz == 300)      b_out   = (const float*)p;
        else if (sz == 2048) {
            if (!b_enc) b_enc = (const float*)p;
            else        b_dec = (const float*)p;
        }
    }
    if (!frames || !cap_ids || !emb || !W_enc || !b_enc || !W_dec || !b_dec ||
        !W_out || !b_out) {
        frames  = (const float*)d_in[0];
        cap_ids = (const int*)  d_in[1];
        emb     = (const float*)d_in[2];
        W_enc   = (const float*)d_in[3];
        b_enc   = (const float*)d_in[4];
        W_dec   = (const float*)d_in[5];
        b_dec   = (const float*)d_in[6];
        W_out   = (const float*)d_in[7];
        b_out   = (const float*)d_in[8];
    }
    float* out = (float*)d_out;

    cudaFuncSetAttribute(lstm_persistent_kernel,
                         cudaFuncAttributeMaxDynamicSharedMemorySize, SM_TOTAL);

    {   // encoder x-projection: [8192 x 2048] @ [2048 x 2048] + b_enc
        dim3 grid(G4 / 128, (BDIM * TENC) / 128);
        gemm_kernel<0><<<grid, 256>>>(frames, W_enc, b_enc, 0, 0,
                                      BDIM * TENC, G4, DIN);
    }
    {   // decoder x-projection with gather: [4096 x 300] @ [300 x 2048] + b_dec
        dim3 grid(G4 / 128, (BDIM * TDEC) / 128);
        gemm_kernel<1><<<grid, 256>>>(emb, W_dec, b_dec, 0, cap_ids,
                                      BDIM * TDEC, G4, DW);
    }

    // persistent recurrence: all 96 steps in one launch
    {
        const float* WhE = W_enc + (long)DIN * G4;
        const float* WhD = W_dec + (long)DW * G4;
        lstm_persistent_kernel<<<dim3(4, 32), 512, SM_TOTAL>>>(WhE, WhD);
    }

    {   // output projection: [4096 x 512] @ [512 x 300] + b_out
        dim3 grid((DW + 127) / 128, (BDIM * TDEC) / 128);
        gemm_kernel<2><<<grid, 256>>>(0, W_out, b_out, out, 0,
                                      BDIM * TDEC, DW, HID);
    }
}

// round 14
// speedup vs baseline: 1.0045x; 1.0045x over previous
#include <cuda_runtime.h>
#include <math.h>

#define BDIM   128
#define TENC   64
#define TDEC   32
#define DIN    2048
#define DW     300
#define HID    512
#define G4     2048   // 4*HID
#define NBLK   128    // persistent grid: 4 b-groups x 32 j-groups

typedef unsigned long long u64;

// ---------------- scratch (device globals: no allocation allowed) -------------
// Referenced ONLY from device code (host-side symbol use = ATS shadow bug).
__device__ float g_pre_enc[BDIM * TENC * G4];   // [b*TENC + t][4H]
__device__ float g_pre_dec[BDIM * TDEC * G4];   // [b*TDEC + t][4H]
__device__ float g_hT[2][HID][BDIM];            // TRANSPOSED hidden state [k][b]
__device__ float g_dechs[TDEC * BDIM * HID];    // decoder h outputs [t][b][h]

// grid barrier state (count returns to 0 after each barrier)
__device__ unsigned g_bar_count = 0;
__device__ volatile unsigned g_bar_gen = 0;

__device__ __forceinline__ float sigm(float x) { return 1.0f / (1.0f + expf(-x)); }

__device__ __forceinline__ u64 ffma2(u64 a, u64 b, u64 c) {
    u64 d;
    asm("fma.rn.f32x2 %0, %1, %2, %3;" : "=l"(d) : "l"(a), "l"(b), "l"(c));
    return d;
}
__device__ __forceinline__ u64 fadd2(u64 a, u64 b) {
    u64 d;
    asm("add.rn.f32x2 %0, %1, %2;" : "=l"(d) : "l"(a), "l"(b));
    return d;
}
__device__ __forceinline__ u64 dup2(float w) {
    u64 d;
    asm("mov.b64 %0, {%1, %1};" : "=l"(d) : "f"(w));
    return d;
}

// two-phase sense-reversing grid barrier; all NBLK blocks co-resident
// (1 block/SM, 128 blocks <= 148 SMs). __nanosleep backoff is load-bearing.
__device__ __forceinline__ void grid_sync() {
    __syncthreads();
    if (threadIdx.x == 0) {
        __threadfence();
        unsigned my = g_bar_gen;
        if (atomicAdd(&g_bar_count, 1) == NBLK - 1) {
            g_bar_count = 0;
            __threadfence();
            g_bar_gen = my + 1;
        } else {
            while (g_bar_gen == my) { __nanosleep(64); }
        }
        __threadfence();
    }
    __syncthreads();
}

// ---------------- double-buffered packed-f32x2 GEMM:  C = A @ W + bias --------
// 128x128 tile, BK=8, 256 threads, one __syncthreads per k-tile.
template <int MODE>
__global__ __launch_bounds__(256, 2)
void gemm_kernel(const float* __restrict__ A, const float* __restrict__ W,
                 const float* __restrict__ bias, float* __restrict__ Cout,
                 const int* __restrict__ ids, int M, int N, int K)
{
    __shared__ float As[2][8][132];
    __shared__ float Bs[2][8][128];

    float* C;
    if (MODE == 0)      C = g_pre_enc;
    else if (MODE == 1) C = g_pre_dec;
    else                C = Cout;

    const int bn0 = blockIdx.x * 128;
    const int bm0 = blockIdx.y * 128;
    const int tid = threadIdx.x;

    const int arow = tid >> 1;          // 0..127
    const int ak   = (tid & 1) * 4;     // 0 or 4
    const int bk   = tid >> 5;          // 0..7
    const int bn   = (tid & 31) * 4;    // 0..124

    const float* arow_ptr;
    if (MODE == 1) {
        arow_ptr = A + (long)ids[bm0 + arow] * K;     // embedding gather
    } else if (MODE == 2) {
        arow_ptr = g_dechs + (long)(bm0 + arow) * K;
    } else {
        arow_ptr = A + (long)(bm0 + arow) * K;
    }

    const int tc = tid & 15;
    const int tr = tid >> 4;

    u64 acc[8][4];
    #pragma unroll
    for (int i = 0; i < 8; i++)
        #pragma unroll
        for (int j = 0; j < 4; j++) acc[i][j] = 0ull;

    // prologue: stage tile 0
    #pragma unroll
    for (int s = 0; s < 4; s++) {
        int k = ak + s;
        As[0][ak + s][arow] = (k < K) ? arow_ptr[k] : 0.0f;
    }
    #pragma unroll
    for (int s = 0; s < 4; s++) {
        int col = bn0 + bn + s;
        Bs[0][bk][bn + s] = (bk < K && col < N) ? W[(long)bk * N + col] : 0.0f;
    }
    __syncthreads();

    for (int kt = 0; kt < K; kt += 8) {
        const int cur = (kt >> 3) & 1;
        const bool has_next = (kt + 8) < K;

        float ra[4], rb[4];
        if (has_next) {
            #pragma unroll
            for (int s = 0; s < 4; s++) {
                int k = kt + 8 + ak + s;
                ra[s] = (k < K) ? arow_ptr[k] : 0.0f;
            }
            #pragma unroll
            for (int s = 0; s < 4; s++) {
                int k = kt + 8 + bk;
                int col = bn0 + bn + s;
                rb[s] = (k < K && col < N) ? W[(long)k * N + col] : 0.0f;
            }
        }

        #pragma unroll
        for (int k = 0; k < 8; k++) {
            float4 a0 = *reinterpret_cast<const float4*>(&As[cur][k][tr * 8]);
            float4 a1 = *reinterpret_cast<const float4*>(&As[cur][k][tr * 8 + 4]);
            u64 a2[8];
            a2[0] = dup2(a0.x); a2[1] = dup2(a0.y);
            a2[2] = dup2(a0.z); a2[3] = dup2(a0.w);
            a2[4] = dup2(a1.x); a2[5] = dup2(a1.y);
            a2[6] = dup2(a1.z); a2[7] = dup2(a1.w);
            const u64* bp = reinterpret_cast<const u64*>(&Bs[cur][k][0]);
            u64 b2[4];
            #pragma unroll
            for (int j = 0; j < 4; j++) b2[j] = bp[tc + 16 * j];
            #pragma unroll
            for (int i = 0; i < 8; i++)
                #pragma unroll
                for (int j = 0; j < 4; j++)
                    acc[i][j] = ffma2(a2[i], b2[j], acc[i][j]);
        }

        if (has_next) {
            #pragma unroll
            for (int s = 0; s < 4; s++) As[1 - cur][ak + s][arow] = ra[s];
            #pragma unroll
            for (int s = 0; s < 4; s++) Bs[1 - cur][bk][bn + s] = rb[s];
        }
        __syncthreads();
    }

    #pragma unroll
    for (int i = 0; i < 8; i++) {
        int m = bm0 + tr * 8 + i;
        #pragma unroll
        for (int j = 0; j < 4; j++) {
            float2 v = *reinterpret_cast<float2*>(&acc[i][j]);
            int n = bn0 + 2 * (tc + 16 * j);
            if (MODE == 2) {
                int b = m & 127, t = m >> 7;    // m = t*128 + b
                long obase = ((long)b * TDEC + t) * (long)N;
                if (n < N)     C[obase + n]     = v.x + bias[n];
                if (n + 1 < N) C[obase + n + 1] = v.y + bias[n + 1];
            } else {
                float* cp = C + (long)m * N + n;
                cp[0] = v.x + bias[n];
                cp[1] = v.y + bias[n + 1];
            }
        }
    }
}

// ---------------- persistent recurrent LSTM (j-pair packed, coalesced I/O) ----
// Block (bg, jg): b0 = bg*32 (32 batches), j0 = jg*16 (8 j-pairs x 4 gates).
// 512 threads = 2 k-halves x (8 jp x 32 b). Warp = fixed jp, lanes = batches.
// Inner k: LDS.32 h + dup + 2x LDS.128 weight broadcast + 4 ffma2.
// Cell state c lives in REGISTERS (each (jp,b) thread owns its pair for all
// 96 steps). pre-activation gates staged through smem (coalesced float4 tile
// load); dechs bounced through smem then stored coalesced.
//
// Dynamic smem:
//   Ws   float[512][64]  131072 B (persistent per phase)
//   hs   float[512][36]   73728 B (per-step transposed h; red aliases it)
//   pres float[32][68]     8704 B (per-step pre-activation tile [b][g*16+jj])
//   dsm  float[32][68]     8704 B (decoder h bounce [b][jj])
#define SM_WS_BYTES   (512 * 64 * 4)
#define SM_HS_BYTES   (512 * 36 * 4)
#define SM_PRES_BYTES (32 * 68 * 4)
#define SM_TOTAL      (SM_WS_BYTES + SM_HS_BYTES + 2 * SM_PRES_BYTES)

__global__ __launch_bounds__(512, 1)
void lstm_persistent_kernel(const float* __restrict__ WhE,
                            const float* __restrict__ WhD)
{
    extern __shared__ char smraw[];
    float (*Ws)[64]   = reinterpret_cast<float(*)[64]>(smraw);
    float (*hs)[36]   = reinterpret_cast<float(*)[36]>(smraw + SM_WS_BYTES);
    u64   (*red)[4]   = reinterpret_cast<u64(*)[4]>(smraw + SM_WS_BYTES);
    float (*pres)[68] = reinterpret_cast<float(*)[68]>(smraw + SM_WS_BYTES + SM_HS_BYTES);
    float (*dsm)[68]  = reinterpret_cast<float(*)[68]>(smraw + SM_WS_BYTES + SM_HS_BYTES + SM_PRES_BYTES);

    const int tid  = threadIdx.x;
    const int half = tid >> 8;          // k in [0,256) / [256,512)
    const int ltid = tid & 255;
    const int b0 = blockIdx.x * 32;
    const int j0 = blockIdx.y * 16;

    const int jp = ltid >> 5;           // 0..7  (j-pair: j0+2jp, j0+2jp+1)
    const int b  = ltid & 31;           // 0..31 (lane = batch)

    // h staging roles
    const int sb = tid & 31;            // batch lane
    const int sk = tid >> 5;            // k row 0..15 (+ it*16)

    // pres staging roles (one float4 per thread)
    const int pb = tid >> 4;            // 0..31
    const int pq = tid & 15;
    const int pgm = pq >> 2;            // gate 0..3
    const int pj4 = (pq & 3) * 4;       // 0,4,8,12

    // ---- init: zero h[0] (transposed); c lives in registers ----
    if (half == 0) {
        int j = j0 + 2 * jp;
        g_hT[0][j][b0 + b] = 0.0f;
        g_hT[0][j + 1][b0 + b] = 0.0f;
    }
    float2 creg = make_float2(0.0f, 0.0f);   // owned (b, j-pair) cell state

    // ---- load encoder weight slice into smem ----
    for (int idx = tid; idx < 512 * 64; idx += 512) {
        int k = idx >> 6, col = idx & 63;
        int jpl = col >> 3, g = (col >> 1) & 3, e = col & 1;
        Ws[k][col] = WhE[(long)k * G4 + g * HID + j0 + 2 * jpl + e];
    }
    // first grid_sync's __syncthreads covers Ws visibility within the block

    for (int s = 0; s < TENC + TDEC; s++) {
        const int phase = (s >= TENC);
        const int t = phase ? s - TENC : s;
        const float* pre = phase ? g_pre_dec : g_pre_enc;
        const int Tdim = phase ? TDEC : TENC;
        const float (*hinT)[BDIM] = g_hT[s & 1];
        float (*houtT)[BDIM] = g_hT[(s + 1) & 1];

        grid_sync();   // previous step's hT visible everywhere

        if (s == TENC) {   // phase switch: decoder weights
            for (int idx = tid; idx < 512 * 64; idx += 512) {
                int k = idx >> 6, col = idx & 63;
                int jpl = col >> 3, g = (col >> 1) & 3, e = col & 1;
                Ws[k][col] = WhD[(long)k * G4 + g * HID + j0 + 2 * jpl + e];
            }
            __syncthreads();
        }

        // ---- stage pres tile (coalesced float4): pres[bb][g*16+jj] ----
        {
            const float* sp = pre + ((long)(b0 + pb) * Tdim + t) * G4
                              + pgm * 512 + j0 + pj4;
            float4 v = *reinterpret_cast<const float4*>(sp);
            *reinterpret_cast<float4*>(&pres[pb][pgm * 16 + pj4]) = v;
        }
        // ---- stage h: hs[k][b] = hT[k][b0+b] (coalesced LDG, clean STS) ----
        #pragma unroll 4
        for (int it = 0; it < 32; it++) {
            int k = sk + it * 16;
            hs[k][sb] = hinT[k][b0 + sb];
        }
        __syncthreads();

        // ---- main FMA loop: per k = LDS.32 + dup + 2x LDS.128(bcast) + 4 ffma2
        u64 acc2[4] = {0ull, 0ull, 0ull, 0ull};
        const int kbase = half << 8;
        #pragma unroll 8
        for (int k = kbase; k < kbase + 256; k++) {
            u64 h2 = dup2(hs[k][b]);
            ulonglong2 w01 = *reinterpret_cast<const ulonglong2*>(&Ws[k][jp * 8]);
            ulonglong2 w23 = *reinterpret_cast<const ulonglong2*>(&Ws[k][jp * 8 + 4]);
            acc2[0] = ffma2(h2, w01.x, acc2[0]);
            acc2[1] = ffma2(h2, w01.y, acc2[1]);
            acc2[2] = ffma2(h2, w23.x, acc2[2]);
            acc2[3] = ffma2(h2, w23.y, acc2[3]);
        }
        __syncthreads();   // compute done before red aliases hs

        if (half == 1) {
            #pragma unroll
            for (int g = 0; g < 4; g++) red[ltid][g] = acc2[g];
        }
        __syncthreads();

        if (half == 0) {
            float2 av[4], pg[4];
            #pragma unroll
            for (int g = 0; g < 4; g++) {
                u64 v = fadd2(acc2[g], red[ltid][g]);
                av[g] = *reinterpret_cast<float2*>(&v);
                pg[g] = make_float2(pres[b][g * 16 + 2 * jp],
                                    pres[b][g * 16 + 2 * jp + 1]);
            }
            int bb = b0 + b;
            int j = j0 + 2 * jp;
            float hn[2], cn[2];
            #pragma unroll
            for (int e = 0; e < 2; e++) {
                float gi = (e ? av[0].y : av[0].x) + (e ? pg[0].y : pg[0].x);
                float gj = (e ? av[1].y : av[1].x) + (e ? pg[1].y : pg[1].x);
                float gf = (e ? av[2].y : av[2].x) + (e ? pg[2].y : pg[2].x);
                float go = (e ? av[3].y : av[3].x) + (e ? pg[3].y : pg[3].x);
                float cv = e ? creg.y : creg.x;
                cn[e] = cv * sigm(gf + 1.0f) + sigm(gi) * tanhf(gj);
                hn[e] = tanhf(cn[e]) * sigm(go);
            }
            creg = make_float2(cn[0], cn[1]);
            houtT[j][bb]     = hn[0];   // coalesced (lanes = b)
            houtT[j + 1][bb] = hn[1];
            dsm[b][2 * jp]     = hn[0]; // bounce for coalesced dechs store
            dsm[b][2 * jp + 1] = hn[1];
        }
        __syncthreads();

        if (phase && tid < 128) {       // coalesced dechs store (float4)
            int bb = tid >> 2;          // 0..31
            int j4 = (tid & 3) * 4;     // 0,4,8,12
            float4 v = make_float4(dsm[bb][j4], dsm[bb][j4 + 1],
                                   dsm[bb][j4 + 2], dsm[bb][j4 + 3]);
            *reinterpret_cast<float4*>(
                &g_dechs[((long)t * BDIM + b0 + bb) * HID + j0 + j4]) = v;
        }
    }
}

// ---------------- launch ------------------------------------------------------
extern "C" void kernel_launch(void* const* d_in, const int* in_sizes, int n_in,
                              void* d_out, int out_size) {
    (void)out_size;
    const float* frames  = 0;   // 16777216
    const int*   cap_ids = 0;   // 4096
    const float* emb     = 0;   // 9600000
    const float* W_enc   = 0;   // 5242880
    const float* b_enc   = 0;   // 2048 (first seen)
    const float* W_dec   = 0;   // 1662976
    const float* b_dec   = 0;   // 2048 (second seen)
    const float* W_out   = 0;   // 153600
    const float* b_out   = 0;   // 300

    for (int i = 0; i < n_in; i++) {
        long sz = in_sizes[i];
        const void* p = d_in[i];
        if      (sz == 16777216) frames  = (const float*)p;
        else if (sz == 4096)     cap_ids = (const int*)p;
        else if (sz == 9600000)  emb     = (const float*)p;
        else if (sz == 5242880)  W_enc   = (const float*)p;
        else if (sz == 1662976)  W_dec   = (const float*)p;
        else if (sz == 153600)   W_out   = (const float*)p;
        else if (sz == 300)      b_out   = (const float*)p;
        else if (sz == 2048) {
            if (!b_enc) b_enc = (const float*)p;
            else        b_dec = (const float*)p;
        }
    }
    if (!frames || !cap_ids || !emb || !W_enc || !b_enc || !W_dec || !b_dec ||
        !W_out || !b_out) {
        frames  = (const float*)d_in[0];
        cap_ids = (const int*)  d_in[1];
        emb     = (const float*)d_in[2];
        W_enc   = (const float*)d_in[3];
        b_enc   = (const float*)d_in[4];
        W_dec   = (const float*)d_in[5];
        b_dec   = (const float*)d_in[6];
        W_out   = (const float*)d_in[7];
        b_out   = (const float*)d_in[8];
    }
    float* out = (float*)d_out;

    cudaFuncSetAttribute(lstm_persistent_kernel,
                         cudaFuncAttributeMaxDynamicSharedMemorySize, SM_TOTAL);

    {   // encoder x-projection: [8192 x 2048] @ [2048 x 2048] + b_enc
        dim3 grid(G4 / 128, (BDIM * TENC) / 128);
        gemm_kernel<0><<<grid, 256>>>(frames, W_enc, b_enc, 0, 0,
                                      BDIM * TENC, G4, DIN);
    }
    {   // decoder x-projection with gather: [4096 x 300] @ [300 x 2048] + b_dec
        dim3 grid(G4 / 128, (BDIM * TDEC) / 128);
        gemm_kernel<1><<<grid, 256>>>(emb, W_dec, b_dec, 0, cap_ids,
                                      BDIM * TDEC, G4, DW);
    }

    // persistent recurrence: all 96 steps in one launch
    {
        const float* WhE = W_enc + (long)DIN * G4;
        const float* WhD = W_dec + (long)DW * G4;
        lstm_persistent_kernel<<<dim3(4, 32), 512, SM_TOTAL>>>(WhE, WhD);
    }

    {   // output projection: [4096 x 512] @ [512 x 300] + b_out
        dim3 grid((DW + 127) / 128, (BDIM * TDEC) / 128);
        gemm_kernel<2><<<grid, 256>>>(0, W_out, b_out, out, 0,
                                      BDIM * TDEC, DW, HID);
    }
}

// round 16
// speedup vs baseline: 1.0559x; 1.0512x over previous
#include <cuda_runtime.h>
#include <math.h>

#define BDIM   128
#define TENC   64
#define TDEC   32
#define DIN    2048
#define DW     300
#define HID    512
#define G4     2048   // 4*HID
#define NBLK   128    // persistent grid: 4 b-groups x 32 j-groups

typedef unsigned long long u64;

// ---------------- scratch (device globals: no allocation allowed) -------------
// Referenced ONLY from device code (host-side symbol use = ATS shadow bug).
__device__ float g_pre_enc[BDIM * TENC * G4];   // [b*TENC + t][4H]
__device__ float g_pre_dec[BDIM * TDEC * G4];   // [b*TDEC + t][4H]
__device__ float g_h[2][BDIM * HID];            // ping-pong hidden state
__device__ float g_c[BDIM * HID];               // cell state (in-place)
__device__ float g_dechs[TDEC * BDIM * HID];    // decoder h outputs [t][b][h]

// grid barrier state (count returns to 0 after each barrier)
__device__ unsigned g_bar_count = 0;
__device__ volatile unsigned g_bar_gen = 0;

__device__ __forceinline__ float sigm(float x) { return 1.0f / (1.0f + expf(-x)); }

__device__ __forceinline__ u64 ffma2(u64 a, u64 b, u64 c) {
    u64 d;
    asm("fma.rn.f32x2 %0, %1, %2, %3;" : "=l"(d) : "l"(a), "l"(b), "l"(c));
    return d;
}
__device__ __forceinline__ u64 fadd2(u64 a, u64 b) {
    u64 d;
    asm("add.rn.f32x2 %0, %1, %2;" : "=l"(d) : "l"(a), "l"(b));
    return d;
}
__device__ __forceinline__ u64 dup2(float w) {
    u64 d;
    asm("mov.b64 %0, {%1, %1};" : "=l"(d) : "f"(w));
    return d;
}

// two-phase sense-reversing grid barrier; all NBLK blocks co-resident
// (1 block/SM, 128 blocks <= 148 SMs). __nanosleep backoff is load-bearing.
__device__ __forceinline__ void grid_sync() {
    __syncthreads();
    if (threadIdx.x == 0) {
        __threadfence();
        unsigned my = g_bar_gen;
        if (atomicAdd(&g_bar_count, 1) == NBLK - 1) {
            g_bar_count = 0;
            __threadfence();
            g_bar_gen = my + 1;
        } else {
            while (g_bar_gen == my) { __nanosleep(32); }
        }
        __threadfence();
    }
    __syncthreads();
}

// ---------------- double-buffered packed-f32x2 GEMM:  C = A @ W + bias --------
// 128x128 tile, BK=8, 256 threads, one __syncthreads per k-tile.
// MODE 0: A = frames [8192 x 2048]      -> writes g_pre_enc (symbol)
// MODE 1: A-row = emb[ids[m]] (K=300)   -> writes g_pre_dec (symbol)
// MODE 2: A = g_dechs (symbol) [4096 x 512], N=300 -> writes Cout (d_out)
template <int MODE>
__global__ __launch_bounds__(256, 2)
void gemm_kernel(const float* __restrict__ A, const float* __restrict__ W,
                 const float* __restrict__ bias, float* __restrict__ Cout,
                 const int* __restrict__ ids, int M, int N, int K)
{
    __shared__ float As[2][8][132];
    __shared__ float Bs[2][8][128];

    float* C;
    if (MODE == 0)      C = g_pre_enc;
    else if (MODE == 1) C = g_pre_dec;
    else                C = Cout;

    const int bn0 = blockIdx.x * 128;
    const int bm0 = blockIdx.y * 128;
    const int tid = threadIdx.x;

    const int arow = tid >> 1;          // 0..127
    const int ak   = (tid & 1) * 4;     // 0 or 4
    const int bk   = tid >> 5;          // 0..7
    const int bn   = (tid & 31) * 4;    // 0..124

    const float* arow_ptr;
    if (MODE == 1) {
        arow_ptr = A + (long)ids[bm0 + arow] * K;     // embedding gather
    } else if (MODE == 2) {
        arow_ptr = g_dechs + (long)(bm0 + arow) * K;
    } else {
        arow_ptr = A + (long)(bm0 + arow) * K;
    }

    const int tc = tid & 15;
    const int tr = tid >> 4;

    u64 acc[8][4];
    #pragma unroll
    for (int i = 0; i < 8; i++)
        #pragma unroll
        for (int j = 0; j < 4; j++) acc[i][j] = 0ull;

    // prologue: stage tile 0
    #pragma unroll
    for (int s = 0; s < 4; s++) {
        int k = ak + s;
        As[0][ak + s][arow] = (k < K) ? arow_ptr[k] : 0.0f;
    }
    #pragma unroll
    for (int s = 0; s < 4; s++) {
        int col = bn0 + bn + s;
        Bs[0][bk][bn + s] = (bk < K && col < N) ? W[(long)bk * N + col] : 0.0f;
    }
    __syncthreads();

    for (int kt = 0; kt < K; kt += 8) {
        const int cur = (kt >> 3) & 1;
        const bool has_next = (kt + 8) < K;

        float ra[4], rb[4];
        if (has_next) {
            #pragma unroll
            for (int s = 0; s < 4; s++) {
                int k = kt + 8 + ak + s;
                ra[s] = (k < K) ? arow_ptr[k] : 0.0f;
            }
            #pragma unroll
            for (int s = 0; s < 4; s++) {
                int k = kt + 8 + bk;
                int col = bn0 + bn + s;
                rb[s] = (k < K && col < N) ? W[(long)k * N + col] : 0.0f;
            }
        }

        #pragma unroll
        for (int k = 0; k < 8; k++) {
            float4 a0 = *reinterpret_cast<const float4*>(&As[cur][k][tr * 8]);
            float4 a1 = *reinterpret_cast<const float4*>(&As[cur][k][tr * 8 + 4]);
            u64 a2[8];
            a2[0] = dup2(a0.x); a2[1] = dup2(a0.y);
            a2[2] = dup2(a0.z); a2[3] = dup2(a0.w);
            a2[4] = dup2(a1.x); a2[5] = dup2(a1.y);
            a2[6] = dup2(a1.z); a2[7] = dup2(a1.w);
            const u64* bp = reinterpret_cast<const u64*>(&Bs[cur][k][0]);
            u64 b2[4];
            #pragma unroll
            for (int j = 0; j < 4; j++) b2[j] = bp[tc + 16 * j];
            #pragma unroll
            for (int i = 0; i < 8; i++)
                #pragma unroll
                for (int j = 0; j < 4; j++)
                    acc[i][j] = ffma2(a2[i], b2[j], acc[i][j]);
        }

        if (has_next) {
            #pragma unroll
            for (int s = 0; s < 4; s++) As[1 - cur][ak + s][arow] = ra[s];
            #pragma unroll
            for (int s = 0; s < 4; s++) Bs[1 - cur][bk][bn + s] = rb[s];
        }
        __syncthreads();
    }

    #pragma unroll
    for (int i = 0; i < 8; i++) {
        int m = bm0 + tr * 8 + i;
        #pragma unroll
        for (int j = 0; j < 4; j++) {
            float2 v = *reinterpret_cast<float2*>(&acc[i][j]);
            int n = bn0 + 2 * (tc + 16 * j);
            if (MODE == 2) {
                int b = m & 127, t = m >> 7;    // m = t*128 + b
                long obase = ((long)b * TDEC + t) * (long)N;
                if (n < N)     C[obase + n]     = v.x + bias[n];
                if (n + 1 < N) C[obase + n + 1] = v.y + bias[n + 1];
            } else {
                float* cp = C + (long)m * N + n;
                cp[0] = v.x + bias[n];
                cp[1] = v.y + bias[n + 1];
            }
        }
    }
}

// ---------------- persistent recurrent LSTM (K11: batch-pair packed) ----------
// Block (bg, jg): b0 = bg*32 (32 batches as 16 pairs (b,b+16)), j0 = jg*16
// (16 j-columns x 4 gates). 512 threads = 2 k-halves x (16 bq x 16 jj).
// Weight tile gate-transposed scalar Ws[k][jj*4+g] -> one LDS.128 fetches all
// 4 gate weights; duplication in registers. h pairs packed in hs2.
//
// Dynamic smem:
//   Ws   float[512][68]  139264 B (persistent per phase)
//   hs2  float2[16][520]  66560 B (per-step h staging; red aliases it)
#define SM_WS_BYTES  (512 * 68 * 4)
#define SM_TOTAL     (SM_WS_BYTES + 16 * 520 * 8)

__global__ __launch_bounds__(512, 1)
void lstm_persistent_kernel(const float* __restrict__ WhE,
                            const float* __restrict__ WhD)
{
    extern __shared__ char smraw[];
    float  (*Ws)[68]   = reinterpret_cast<float(*)[68]>(smraw);
    float2 (*hs2)[520] = reinterpret_cast<float2(*)[520]>(smraw + SM_WS_BYTES);
    u64    (*red)[4]   = reinterpret_cast<u64(*)[4]>(smraw + SM_WS_BYTES);

    const int tid  = threadIdx.x;
    const int half = tid >> 8;          // k in [0,256) / [256,512)
    const int ltid = tid & 255;
    const int b0 = blockIdx.x * 32;
    const int j0 = blockIdx.y * 16;

    const int jj = ltid & 15;
    const int bq = ltid >> 4;           // 0..15 (b pair: b0+bq, b0+bq+16)

    // h-staging roles: warp w loads rows (b0+w, b0+w+16) over full k
    const int bqw  = tid >> 5;          // 0..15
    const int lane = tid & 31;

    // ---- init: zero this block's slice of h[0] and c ----
    {
        int bb = tid >> 4, jl = tid & 15;   // 32 x 16
        g_h[0][(b0 + bb) * HID + j0 + jl] = 0.0f;
        g_c[(b0 + bb) * HID + j0 + jl] = 0.0f;
    }

    // ---- load encoder weight slice into smem ----
    for (int idx = tid; idx < 512 * 64; idx += 512) {
        int jjl = idx & 15;
        int k   = (idx >> 4) & 511;
        int g   = idx >> 13;            // 0..3
        Ws[k][jjl * 4 + g] = WhE[(long)k * G4 + g * HID + j0 + jjl];
    }
    // first grid_sync's __syncthreads covers Ws visibility within the block

    for (int s = 0; s < TENC + TDEC; s++) {
        const int phase = (s >= TENC);
        const int t = phase ? s - TENC : s;
        const float* pre = phase ? g_pre_dec : g_pre_enc;
        const int Tdim = phase ? TDEC : TENC;
        const float* hin = g_h[s & 1];
        float* hout = g_h[(s + 1) & 1];
        float* dechs = phase ? (g_dechs + (long)t * BDIM * HID) : (float*)0;

        grid_sync();   // previous step's h (or init) visible everywhere

        if (s == TENC) {   // phase switch: decoder weights
            for (int idx = tid; idx < 512 * 64; idx += 512) {
                int jjl = idx & 15;
                int k   = (idx >> 4) & 511;
                int g   = idx >> 13;
                Ws[k][jjl * 4 + g] = WhD[(long)k * G4 + g * HID + j0 + jjl];
            }
            __syncthreads();
        }

        // ---- stage h tile: hs2[bq][k] = (h[b0+bq][k], h[b0+bq+16][k]) ----
        {
            const float* r0 = hin + (long)(b0 + bqw) * HID;
            const float* r1 = hin + (long)(b0 + bqw + 16) * HID;
            #pragma unroll
            for (int it = 0; it < 4; it++) {
                int k4 = lane * 4 + it * 128;
                float4 lo = *reinterpret_cast<const float4*>(r0 + k4);
                float4 hi = *reinterpret_cast<const float4*>(r1 + k4);
                hs2[bqw][k4 + 0] = make_float2(lo.x, hi.x);
                hs2[bqw][k4 + 1] = make_float2(lo.y, hi.y);
                hs2[bqw][k4 + 2] = make_float2(lo.z, hi.z);
                hs2[bqw][k4 + 3] = make_float2(lo.w, hi.w);
            }
        }
        __syncthreads();

        // ---- prefetch pre-activation gates (latency hidden under k-loop) ----
        float prv[2][4];
        if (half == 0) {
            #pragma unroll
            for (int bl = 0; bl < 2; bl++) {
                const float* pr = pre +
                    ((long)(b0 + bq + bl * 16) * Tdim + t) * G4 + j0 + jj;
                prv[bl][0] = pr[0];
                prv[bl][1] = pr[512];
                prv[bl][2] = pr[1024];
                prv[bl][3] = pr[1536];
            }
        }

        // ---- main FMA loop (all operands in smem) ----
        u64 acc2[4] = {0ull, 0ull, 0ull, 0ull};
        const int kbase = half << 8;
        #pragma unroll 8
        for (int k = kbase; k < kbase + 256; k++) {
            u64 h2 = *reinterpret_cast<const u64*>(&hs2[bq][k]);
            float4 wv = *reinterpret_cast<const float4*>(&Ws[k][jj * 4]);
            acc2[0] = ffma2(h2, dup2(wv.x), acc2[0]);
            acc2[1] = ffma2(h2, dup2(wv.y), acc2[1]);
            acc2[2] = ffma2(h2, dup2(wv.z), acc2[2]);
            acc2[3] = ffma2(h2, dup2(wv.w), acc2[3]);
        }
        __syncthreads();   // compute done before red aliases hs2

        if (half == 1) {
            #pragma unroll
            for (int g = 0; g < 4; g++) red[ltid][g] = acc2[g];
        }
        __syncthreads();

        if (half == 0) {
            float2 av[4];
            #pragma unroll
            for (int g = 0; g < 4; g++) {
                u64 v = fadd2(acc2[g], red[ltid][g]);
                av[g] = *reinterpret_cast<float2*>(&v);
            }
            #pragma unroll
            for (int bl = 0; bl < 2; bl++) {
                int b = b0 + bq + bl * 16;
                int j = j0 + jj;
                float gi = (bl ? av[0].y : av[0].x) + prv[bl][0];
                float gj = (bl ? av[1].y : av[1].x) + prv[bl][1];
                float gf = (bl ? av[2].y : av[2].x) + prv[bl][2];
                float go = (bl ? av[3].y : av[3].x) + prv[bl][3];
                int idx = b * HID + j;
                float cn = g_c[idx] * sigm(gf + 1.0f) + sigm(gi) * tanhf(gj);
                g_c[idx] = cn;
                float hn = tanhf(cn) * sigm(go);
                hout[idx] = hn;
                if (dechs) dechs[idx] = hn;
            }
        }
    }
}

// ---------------- launch ------------------------------------------------------
extern "C" void kernel_launch(void* const* d_in, const int* in_sizes, int n_in,
                              void* d_out, int out_size) {
    (void)out_size;
    const float* frames  = 0;   // 16777216
    const int*   cap_ids = 0;   // 4096
    const float* emb     = 0;   // 9600000
    const float* W_enc   = 0;   // 5242880
    const float* b_enc   = 0;   // 2048 (first seen)
    const float* W_dec   = 0;   // 1662976
    const float* b_dec   = 0;   // 2048 (second seen)
    const float* W_out   = 0;   // 153600
    const float* b_out   = 0;   // 300

    for (int i = 0; i < n_in; i++) {
        long sz = in_sizes[i];
        const void* p = d_in[i];
        if      (sz == 16777216) frames  = (const float*)p;
        else if (sz == 4096)     cap_ids = (const int*)p;
        else if (sz == 9600000)  emb     = (const float*)p;
        else if (sz == 5242880)  W_enc   = (const float*)p;
        else if (sz == 1662976)  W_dec   = (const float*)p;
        else if (sz == 153600)   W_out   = (const float*)p;
        else if (sz == 300)      b_out   = (const float*)p;
        else if (sz == 2048) {
            if (!b_enc) b_enc = (const float*)p;
            else        b_dec = (const float*)p;
        }
    }
    if (!frames || !cap_ids || !emb || !W_enc || !b_enc || !W_dec || !b_dec ||
        !W_out || !b_out) {
        frames  = (const float*)d_in[0];
        cap_ids = (const int*)  d_in[1];
        emb     = (const float*)d_in[2];
        W_enc   = (const float*)d_in[3];
        b_enc   = (const float*)d_in[4];
        W_dec   = (const float*)d_in[5];
        b_dec   = (const float*)d_in[6];
        W_out   = (const float*)d_in[7];
        b_out   = (const float*)d_in[8];
    }
    float* out = (float*)d_out;

    cudaFuncSetAttribute(lstm_persistent_kernel,
                         cudaFuncAttributeMaxDynamicSharedMemorySize, SM_TOTAL);

    {   // encoder x-projection: [8192 x 2048] @ [2048 x 2048] + b_enc
        dim3 grid(G4 / 128, (BDIM * TENC) / 128);
        gemm_kernel<0><<<grid, 256>>>(frames, W_enc, b_enc, 0, 0,
                                      BDIM * TENC, G4, DIN);
    }
    {   // decoder x-projection with gather: [4096 x 300] @ [300 x 2048] + b_dec
        dim3 grid(G4 / 128, (BDIM * TDEC) / 128);
        gemm_kernel<1><<<grid, 256>>>(emb, W_dec, b_dec, 0, cap_ids,
                                      BDIM * TDEC, G4, DW);
    }

    // persistent recurrence: all 96 steps in one launch
    {
        const float* WhE = W_enc + (long)DIN * G4;
        const float* WhD = W_dec + (long)DW * G4;
        lstm_persistent_kernel<<<dim3(4, 32), 512, SM_TOTAL>>>(WhE, WhD);
    }

    {   // output projection: [4096 x 512] @ [512 x 300] + b_out
        dim3 grid((DW + 127) / 128, (BDIM * TDEC) / 128);
        gemm_kernel<2><<<grid, 256>>>(0, W_out, b_out, out, 0,
                                      BDIM * TDEC, DW, HID);
    }
}